// round 1
// baseline (speedup 1.0000x reference)
#include <cuda_runtime.h>
#include <math.h>

#define NUMR    100
#define NVSC    32
#define DOFN    6
#define BATCH   2048
#define NVAR    192
#define NEQC    30
#define NHDIM   222
#define MAXIT   15
#define SPB     8
#define NTHREADS 256

// shared memory float offsets
#define OFF_XT4  0        // 3*25*32 float4 = 9600 floats  (X transposed, r-chunked)
#define OFF_X4   9600     // 3*100*9 float4 = 10800 floats (X row-major, padded row=9 float4)
#define OFF_Y    20400    // SPB * 3 * 600 = 14400 floats
#define OFF_W    34800    // SPB * 600 = 4800 floats (u / w scratch)
#define OFF_RHS  39600    // SPB * 192
#define OFF_PRIM 41136    // SPB * 192
#define OFF_Q    42672    // 16 * 193 = 3088
#define SMEM_FLOATS 45760 // 183,040 bytes

__device__ __forceinline__ float dot4(float4 a, float4 b) {
    return a.x*b.x + a.y*b.y + a.z*b.z + a.w*b.w;
}

__global__ void __launch_bounds__(NTHREADS, 1)
proj_filter_kernel(const float* __restrict__ lamda,
                   const float* __restrict__ c_in_g,
                   const float* __restrict__ c_samp,
                   const float* __restrict__ b_eq,
                   const float* __restrict__ Av,
                   const float* __restrict__ Aa,
                   const float* __restrict__ Ap,
                   const float* __restrict__ Qi,
                   float* __restrict__ out)
{
    extern __shared__ float sm[];
    const int tid  = threadIdx.x;
    const int warp = tid >> 5;
    const int lane = tid & 31;
    const int s    = blockIdx.x * SPB + warp;

    // ---- stage X matrices (top-left 100x32 block of each kron'd A) ----
    for (int idx = tid; idx < 3 * NUMR * NVSC; idx += NTHREADS) {
        int t   = idx / (NUMR * NVSC);
        int rem = idx - t * (NUMR * NVSC);
        int r = rem >> 5;
        int c = rem & 31;
        const float* Asrc = (t == 0) ? Av : ((t == 1) ? Aa : Ap);
        float v = Asrc[r * NVAR + c];
        // transposed, r in chunks of 4: float idx = ((t*25 + r/4)*32 + c)*4 + (r%4)
        sm[OFF_XT4 + ((t * 25 + (r >> 2)) * 32 + c) * 4 + (r & 3)] = v;
        // row-major padded: ((t*100 + r)*9 + c/4)*4 + (c%4)
        sm[OFF_X4 + ((t * NUMR + r) * 9 + (c >> 2)) * 4 + (c & 3)] = v;
    }
    __syncthreads();

    const float Vb[3] = {0.8f, 1.8f, 3.14159265358979323846f};

    const int yb    = OFF_Y    + warp * 1800;
    const int wb    = OFF_W    + warp * 600;
    const int rbase = OFF_RHS  + warp * 192;
    const int pbase = OFF_PRIM + warp * 192;

    // ---- per-sample register state ----
    float cin[6], cprev[6], pbv[6], l[3][6];
#pragma unroll
    for (int m = 0; m < 6; m++) {
        cin[m]   = c_in_g[s * NVAR + m * 32 + lane];
        cprev[m] = c_samp[s * NVAR + m * 32 + lane];
    }
#pragma unroll
    for (int t = 0; t < 3; t++)
#pragma unroll
        for (int m = 0; m < 6; m++)
            l[t][m] = lamda[s * (3 * NVAR) + t * NVAR + m * 32 + lane];

    // pb = Q_inv[:192,192:222] @ b_eq   (iteration-invariant)
#pragma unroll
    for (int m = 0; m < 6; m++) {
        float a = 0.f;
        int j = m * 32 + lane;
        for (int k = 0; k < NEQC; k++)
            a += Qi[j * NHDIM + NVAR + k] * b_eq[s * NEQC + k];
        pbv[m] = a;
    }

    // ---- init y = c_samples @ X^T per dof per type ----
#pragma unroll
    for (int m = 0; m < 6; m++) sm[pbase + m * 32 + lane] = cprev[m];
    __syncwarp();
    for (int t = 0; t < 3; t++) {
        for (int rr = lane; rr < NUMR; rr += 32) {
            const float4* xr = (const float4*)&sm[OFF_X4] + (t * NUMR + rr) * 9;
            float4 x0 = xr[0], x1 = xr[1], x2 = xr[2], x3 = xr[3];
            float4 x4 = xr[4], x5 = xr[5], x6 = xr[6], x7 = xr[7];
#pragma unroll
            for (int d = 0; d < 6; d++) {
                const float4* pp = (const float4*)&sm[pbase] + d * 8;
                float a = dot4(x0, pp[0]) + dot4(x1, pp[1]) + dot4(x2, pp[2]) + dot4(x3, pp[3])
                        + dot4(x4, pp[4]) + dot4(x5, pp[5]) + dot4(x6, pp[6]) + dot4(x7, pp[7]);
                sm[yb + t * 600 + d * NUMR + rr] = a;
            }
        }
    }
    __syncwarp();

    float fp_sum = 0.f, rp_sum = 0.f;

    for (int it = 0; it < MAXIT; it++) {
        // ======== phase A: rhs = -lincost = lv+la+lp+cin + sum_t u_t @ X_t ========
        float acc[6];
#pragma unroll
        for (int m = 0; m < 6; m++) acc[m] = l[0][m] + l[1][m] + l[2][m] + cin[m];

        for (int t = 0; t < 3; t++) {
            float V = Vb[t];
            for (int i = lane; i < 600; i += 32) {
                float y = sm[yb + t * 600 + i];
                sm[wb + i] = fminf(V, y) - fminf(V, -y);   // (b-s)_top - (b-s)_bot
            }
            __syncwarp();
            const float4* XT = (const float4*)&sm[OFF_XT4] + t * 25 * 32;
            const float4* W4 = (const float4*)&sm[wb];
            for (int rbk = 0; rbk < 25; rbk++) {
                float4 xt = XT[rbk * 32 + lane];
#pragma unroll
                for (int d = 0; d < 6; d++) {
                    float4 u4 = W4[d * 25 + rbk];
                    acc[d] += dot4(xt, u4);
                }
            }
            __syncwarp();
        }
#pragma unroll
        for (int m = 0; m < 6; m++) sm[rbase + m * 32 + lane] = acc[m];

        // ======== phase B: primal = Q_inv[:192,:192] @ rhs + pb (CTA-tiled) ========
        float pr[6];
#pragma unroll
        for (int m = 0; m < 6; m++) pr[m] = pbv[m];
        for (int kc = 0; kc < 12; kc++) {
            __syncthreads();
#pragma unroll
            for (int ii = 0; ii < 12; ii++) {
                int idx = tid + ii * NTHREADS;      // 12*256 = 3072 = 192*16
                int j = idx >> 4, kk = idx & 15;
                sm[OFF_Q + kk * 193 + j] = Qi[j * NHDIM + kc * 16 + kk];
            }
            __syncthreads();
#pragma unroll
            for (int kk = 0; kk < 16; kk++) {
                float rv = sm[rbase + kc * 16 + kk];
#pragma unroll
                for (int m = 0; m < 6; m++)
                    pr[m] += sm[OFF_Q + kk * 193 + lane + 32 * m] * rv;
            }
        }

        // ======== phase C: y update, residuals, slack/lambda updates, norms ========
#pragma unroll
        for (int m = 0; m < 6; m++) sm[pbase + m * 32 + lane] = pr[m];
        float dc = 0.f;
#pragma unroll
        for (int m = 0; m < 6; m++) {
            float dd = pr[m] - cprev[m];
            dc += dd * dd;
            cprev[m] = pr[m];
        }
        __syncwarp();

        float resn[3], dsn[3], dln[3];
        for (int t = 0; t < 3; t++) {
            float V = Vb[t];
            float ra = 0.f, da = 0.f;
            for (int rr = lane; rr < NUMR; rr += 32) {
                const float4* xr = (const float4*)&sm[OFF_X4] + (t * NUMR + rr) * 9;
                float4 x0 = xr[0], x1 = xr[1], x2 = xr[2], x3 = xr[3];
                float4 x4 = xr[4], x5 = xr[5], x6 = xr[6], x7 = xr[7];
#pragma unroll
                for (int d = 0; d < 6; d++) {
                    const float4* pp = (const float4*)&sm[pbase] + d * 8;
                    float yn = dot4(x0, pp[0]) + dot4(x1, pp[1]) + dot4(x2, pp[2]) + dot4(x3, pp[3])
                             + dot4(x4, pp[4]) + dot4(x5, pp[5]) + dot4(x6, pp[6]) + dot4(x7, pp[7]);
                    int i = t * 600 + d * NUMR + rr;
                    float yo = sm[yb + i];
                    float rt  = fmaxf(yn - V, 0.f);     // res top
                    float rbm = fmaxf(-yn - V, 0.f);    // res bottom
                    ra += rt * rt + rbm * rbm;
                    float d1 = fmaxf(V - yn, 0.f) - fmaxf(V - yo, 0.f);
                    float d2 = fmaxf(V + yn, 0.f) - fmaxf(V + yo, 0.f);
                    da += d1 * d1 + d2 * d2;
                    sm[yb + i] = yn;
                    sm[wb + d * NUMR + rr] = rt - rbm;  // res coefficient onto +X
                }
            }
            resn[t] = ra;
            dsn[t]  = da;
            __syncwarp();
            // lambda update: dl = w @ X ; l -= dl
            float dl[6] = {0.f, 0.f, 0.f, 0.f, 0.f, 0.f};
            const float4* XT = (const float4*)&sm[OFF_XT4] + t * 25 * 32;
            const float4* W4 = (const float4*)&sm[wb];
            for (int rbk = 0; rbk < 25; rbk++) {
                float4 xt = XT[rbk * 32 + lane];
#pragma unroll
                for (int d = 0; d < 6; d++)
                    dl[d] += dot4(xt, W4[d * 25 + rbk]);
            }
            float dls = 0.f;
#pragma unroll
            for (int d = 0; d < 6; d++) {
                l[t][d] -= dl[d];
                dls += dl[d] * dl[d];
            }
            dln[t] = dls;
            __syncwarp();
        }

        // warp reductions of the 10 squared norms
        float red[10] = {resn[0], resn[1], resn[2],
                         dsn[0],  dsn[1],  dsn[2],
                         dln[0],  dln[1],  dln[2], dc};
#pragma unroll
        for (int off = 16; off; off >>= 1)
#pragma unroll
            for (int q = 0; q < 10; q++)
                red[q] += __shfl_xor_sync(0xffffffffu, red[q], off);

        rp_sum += sqrtf(red[0]) + sqrtf(red[1]) + sqrtf(red[2]);
        fp_sum += sqrtf(red[3]) + sqrtf(red[4]) + sqrtf(red[5])
                + sqrtf(red[6]) + sqrtf(red[7]) + sqrtf(red[8]) + sqrtf(red[9]);
    }

    // ---- outputs: [c_out (B,192)] [avg_res_fixed_point (B)] [avg_res_primal (B)] ----
#pragma unroll
    for (int m = 0; m < 6; m++)
        out[s * NVAR + m * 32 + lane] = cprev[m];
    if (lane == 0) {
        out[BATCH * NVAR + s]         = fp_sum * (1.0f / MAXIT);
        out[BATCH * NVAR + BATCH + s] = rp_sum * (1.0f / MAXIT);
    }
}

extern "C" void kernel_launch(void* const* d_in, const int* in_sizes, int n_in,
                              void* d_out, int out_size)
{
    const float* lamda = (const float*)d_in[0];
    const float* c_in  = (const float*)d_in[1];
    const float* c_s   = (const float*)d_in[2];
    const float* b_eq  = (const float*)d_in[3];
    const float* Av    = (const float*)d_in[4];
    const float* Aa    = (const float*)d_in[5];
    const float* Ap    = (const float*)d_in[6];
    const float* Qi    = (const float*)d_in[7];
    float* out = (float*)d_out;

    int smem_bytes = SMEM_FLOATS * sizeof(float);
    cudaFuncSetAttribute(proj_filter_kernel,
                         cudaFuncAttributeMaxDynamicSharedMemorySize, smem_bytes);
    proj_filter_kernel<<<BATCH / SPB, NTHREADS, smem_bytes>>>(
        lamda, c_in, c_s, b_eq, Av, Aa, Ap, Qi, out);
}